// round 13
// baseline (speedup 1.0000x reference)
#include <cuda_runtime.h>
#include <math.h>

#define NN 8192
#define DD 128
#define DEG 26
#define NC (DEG + 1)
#define NPART 128

// ---------------- scratch (device globals; no allocations) ----------------
__device__ float g_Xd[NN * DD];      // Z @ W_D^T
__device__ float g_Xc[NN * DD];      // Z @ W_C^T
__device__ float g_Hh[NN * DD];      // tanh(Z @ W1^T + b1)
__device__ float g_rea[NN * DD];     // H @ W2^T + b2
__device__ float g_dif[NN * DD];     // A_norm @ Xd (pre-relu)
__device__ float g_s[NN];            // Z @ w_V
__device__ float g_B[32 * 32];       // separable poly combination matrix
__device__ float g_scal[8];          // omega, delta, center, inv2h
__device__ float g_part[NPART * NC * DD];
__device__ float g_G[NC * DD];       // reduced moments
__device__ float g_G2[NC];           // scalar moments

// ---------------- 64x128 register-tiled SGEMM ----------------
__device__ __forceinline__ void gemm_tile(const float* __restrict__ In,
                                          const float* __restrict__ W,
                                          const float* __restrict__ bias,
                                          float* __restrict__ Out,
                                          int row0, bool doTanh) {
    __shared__ float Zs[32][68];
    __shared__ float Ws[32][132];
    const int tid = threadIdx.x;           // 256 threads
    const int tx = tid & 31, ty = tid >> 5;
    const int c0 = tx * 4, r0 = ty * 8;
    float4 acc[8];
#pragma unroll
    for (int i = 0; i < 8; i++) acc[i] = make_float4(0.f, 0.f, 0.f, 0.f);

    for (int kc = 0; kc < 128; kc += 32) {
#pragma unroll
        for (int i = 0; i < 8; i++) {
            int idx = tid + i * 256;
            int r = idx >> 5, k = idx & 31;
            Zs[k][r] = In[(size_t)(row0 + r) * 128 + kc + k];
        }
#pragma unroll
        for (int i = 0; i < 16; i++) {
            int idx = tid + i * 256;
            int c = idx >> 5, k = idx & 31;
            Ws[k][c] = W[(size_t)c * 128 + kc + k];
        }
        __syncthreads();
#pragma unroll
        for (int k = 0; k < 32; k++) {
            float4 w  = *(const float4*)&Ws[k][c0];
            float4 z0 = *(const float4*)&Zs[k][r0];
            float4 z1 = *(const float4*)&Zs[k][r0 + 4];
            acc[0].x += z0.x * w.x; acc[0].y += z0.x * w.y; acc[0].z += z0.x * w.z; acc[0].w += z0.x * w.w;
            acc[1].x += z0.y * w.x; acc[1].y += z0.y * w.y; acc[1].z += z0.y * w.z; acc[1].w += z0.y * w.w;
            acc[2].x += z0.z * w.x; acc[2].y += z0.z * w.y; acc[2].z += z0.z * w.z; acc[2].w += z0.z * w.w;
            acc[3].x += z0.w * w.x; acc[3].y += z0.w * w.y; acc[3].z += z0.w * w.z; acc[3].w += z0.w * w.w;
            acc[4].x += z1.x * w.x; acc[4].y += z1.x * w.y; acc[4].z += z1.x * w.z; acc[4].w += z1.x * w.w;
            acc[5].x += z1.y * w.x; acc[5].y += z1.y * w.y; acc[5].z += z1.y * w.z; acc[5].w += z1.y * w.w;
            acc[6].x += z1.z * w.x; acc[6].y += z1.z * w.y; acc[6].z += z1.z * w.z; acc[6].w += z1.z * w.w;
            acc[7].x += z1.w * w.x; acc[7].y += z1.w * w.y; acc[7].z += z1.w * w.z; acc[7].w += z1.w * w.w;
        }
        __syncthreads();
    }
    float4 bv = make_float4(0.f, 0.f, 0.f, 0.f);
    if (bias) bv = *(const float4*)&bias[c0];
#pragma unroll
    for (int i = 0; i < 8; i++) {
        float4 v = acc[i];
        v.x += bv.x; v.y += bv.y; v.z += bv.z; v.w += bv.w;
        if (doTanh) { v.x = tanhf(v.x); v.y = tanhf(v.y); v.z = tanhf(v.z); v.w = tanhf(v.w); }
        *(float4*)&Out[(size_t)(row0 + r0 + i) * 128 + c0] = v;
    }
}

// ---------------- s = Z @ w_V ----------------
__global__ void k_s(const float* __restrict__ Z, const float* __restrict__ wv) {
    int warp = (blockIdx.x * blockDim.x + threadIdx.x) >> 5;   // 8192 warps
    int lane = threadIdx.x & 31;
    const float* z = Z + (size_t)warp * 128;
    float acc = z[lane] * wv[lane] + z[lane + 32] * wv[lane + 32] +
                z[lane + 64] * wv[lane + 64] + z[lane + 96] * wv[lane + 96];
#pragma unroll
    for (int o = 16; o > 0; o >>= 1) acc += __shfl_xor_sync(0xffffffffu, acc, o);
    if (lane == 0) g_s[warp] = acc;
}

// ---------------- A: three GEMMs ----------------
__global__ void k_A(const float* __restrict__ Z, const float* __restrict__ WD,
                    const float* __restrict__ WC, const float* __restrict__ W1,
                    const float* __restrict__ b1) {
    int which = blockIdx.x >> 7;
    int row0 = (blockIdx.x & 127) * 64;
    if (which == 0)      gemm_tile(Z, WD, nullptr, g_Xd, row0, false);
    else if (which == 1) gemm_tile(Z, WC, nullptr, g_Xc, row0, false);
    else                 gemm_tile(Z, W1, b1,      g_Hh, row0, true);
}

// ---------------- rea = Hh @ W2^T + b2 ----------------
__global__ void k_rea(const float* __restrict__ W2, const float* __restrict__ b2) {
    gemm_tile(g_Hh, W2, b2, g_rea, blockIdx.x * 64, false);
}

// ---------------- setup: minmax + Chebyshev fit + B matrix ----------------
__global__ void k_setup(const float* __restrict__ om_l, const float* __restrict__ dl_l) {
    const int t = threadIdx.x;             // 1024 threads
    const int wid = t >> 5, lane = t & 31;
    __shared__ float slo[1024], shi[1024];
    __shared__ double sh_fm[64], sh_th[64];
    __shared__ double sh_cs[NC];
    __shared__ double sh_bm[32];
    __shared__ double sh_pas[32][33];
    __shared__ double sh_hc[2];

    float lo = 1e30f, hi = -1e30f;
#pragma unroll
    for (int r = 0; r < 8; r++) { float v = g_s[t + r * 1024]; lo = fminf(lo, v); hi = fmaxf(hi, v); }
    slo[t] = lo; shi[t] = hi; __syncthreads();
    for (int st = 512; st > 0; st >>= 1) {
        if (t < st) { slo[t] = fminf(slo[t], slo[t + st]); shi[t] = fmaxf(shi[t], shi[t + st]); }
        __syncthreads();
    }
    if (t == 0) {
        double dlo = (double)slo[0], dhi = (double)shi[0];
        sh_hc[0] = 0.5 * (dlo + dhi);
        sh_hc[1] = 0.5 * (dhi - dlo) + 1e-12;
    }
    __syncthreads();
    const double half = sh_hc[1];
    const double PI = 3.14159265358979323846;

    if (t < 64) {
        double th = PI * (t + 0.5) / 64.0;
        double vm = cos(th);
        sh_th[t] = th;
        sh_fm[t] = exp(1.0 / (1.0 + exp(-2.0 * half * vm)));
    }
    __syncthreads();

    if (wid < NC) {
        double acc = sh_fm[lane] * cos((double)wid * sh_th[lane])
                   + sh_fm[lane + 32] * cos((double)wid * sh_th[lane + 32]);
#pragma unroll
        for (int o = 16; o > 0; o >>= 1)
            acc += __shfl_xor_sync(0xffffffffu, acc, o);
        if (lane == 0) sh_cs[wid] = acc * (2.0 / 64.0) * (wid == 0 ? 0.5 : 1.0);
    }
    if (wid == 31) {                           // Pascal's triangle
        double cur = (lane == 0) ? 1.0 : 0.0;
        sh_pas[0][lane] = cur;
        for (int n = 1; n < 32; n++) {
            double up = __shfl_up_sync(0xffffffffu, cur, 1);
            if (lane == 0) up = 0.0;
            cur += up;
            sh_pas[n][lane] = cur;
        }
    }
    __syncthreads();

    if (wid == 0) {                            // Chebyshev -> monomial
        double mprev = (lane == 0) ? 1.0 : 0.0;
        double mcur  = (lane == 1) ? 1.0 : 0.0;
        double bm = sh_cs[0] * mprev + sh_cs[1] * mcur;
        for (int k = 2; k < NC; k++) {
            double sh = __shfl_up_sync(0xffffffffu, mcur, 1);
            if (lane == 0) sh = 0.0;
            double mnext = 2.0 * sh - mprev;
            bm += sh_cs[k] * mnext;
            mprev = mcur; mcur = mnext;
        }
        sh_bm[lane] = bm;
    }
    __syncthreads();

    {
        int l = t >> 5, p = t & 31;
        float val = 0.f;
        if (l <= DEG && p <= DEG - l) {
            double v = sh_bm[l + p] * sh_pas[l + p][l];
            if (p & 1) v = -v;
            val = (float)v;
        }
        g_B[t] = val;
    }
    if (t == 0) {
        g_scal[0] = 1.f / (1.f + expf(-om_l[0]));  // omega
        g_scal[1] = 1.f / (1.f + expf(-dl_l[0]));  // delta
        g_scal[2] = (float)sh_hc[0];               // center
        g_scal[3] = (float)(0.5 / half);           // 1/(2*half)
    }
}

// ---------------- moments: G_p partials + scalar moments ----------------
__global__ void k_mom() {
    int bx = blockIdx.x;      // 65 blocks
    int tid = threadIdx.x;    // 256
    float center = g_scal[2], inv2h = g_scal[3];
    if (bx < 64) {
        int h = tid >> 7, d = tid & 127;
        int part = bx * 2 + h;
        int j0 = bx * 128 + h * 64;
        float acc[NC];
#pragma unroll
        for (int p = 0; p < NC; p++) acc[p] = 0.f;
#pragma unroll 2
        for (int jj = 0; jj < 64; jj++) {
            int j = j0 + jj;
            float sig = (g_s[j] - center) * inv2h;
            float x = g_Xc[(size_t)j * 128 + d];
            float sig2 = sig * sig;
            float pe = x, po = x * sig;
            acc[0] += pe; acc[1] += po;
#pragma unroll
            for (int p = 2; p < NC; p += 2) {
                pe *= sig2; acc[p] += pe;
                if (p + 1 < NC) { po *= sig2; acc[p + 1] += po; }
            }
        }
#pragma unroll
        for (int p = 0; p < NC; p++) g_part[((size_t)part * NC + p) * 128 + d] = acc[p];
    } else {
        float acc[NC];
#pragma unroll
        for (int p = 0; p < NC; p++) acc[p] = 0.f;
#pragma unroll 2
        for (int jj = 0; jj < 32; jj++) {
            int j = tid + jj * 256;
            float sig = (g_s[j] - center) * inv2h;
            float sig2 = sig * sig;
            float pe = 1.f, po = sig;
            acc[0] += pe; acc[1] += po;
#pragma unroll
            for (int p = 2; p < NC; p += 2) {
                pe *= sig2; acc[p] += pe;
                if (p + 1 < NC) { po *= sig2; acc[p + 1] += po; }
            }
        }
        __shared__ float red2[8][NC];
        int wid = tid >> 5, lane = tid & 31;
#pragma unroll
        for (int p = 0; p < NC; p++) {
            float v = acc[p];
#pragma unroll
            for (int o = 16; o > 0; o >>= 1) v += __shfl_xor_sync(0xffffffffu, v, o);
            if (lane == 0) red2[wid][p] = v;
        }
        __syncthreads();
        if (tid < NC) {
            float s = 0.f;
#pragma unroll
            for (int w = 0; w < 8; w++) s += red2[w][tid];
            g_G2[tid] = s;
        }
    }
}

// ---------------- spmm: cp.async-staged A stream, warp per row ---------------
#define SP_CAP 64
#define CPT 4     // chunks per tile (chunk = 32 float4 = 512B per warp)
#define NT 16     // tiles per row (64 chunks total)

__global__ void __launch_bounds__(128, 12)
k_spmm(const float* __restrict__ A) {
    __shared__ __align__(16) float4 s_a[4][2][CPT][32];   // 16KB
    __shared__ float s_val[4][SP_CAP];
    __shared__ int   s_col[4][SP_CAP];
    const int wid = threadIdx.x >> 5;
    const int lane = threadIdx.x & 31;
    const int row = blockIdx.x * 4 + wid;
    const float4* __restrict__ Ar = (const float4*)(A + (size_t)row * NN);
    const float4* __restrict__ X4 = (const float4*)g_Xd;
    float4 acc = make_float4(0.f, 0.f, 0.f, 0.f);

    // prologue: stage tile 0
#pragma unroll
    for (int i = 0; i < CPT; i++) {
        unsigned dst = (unsigned)__cvta_generic_to_shared(&s_a[wid][0][i][lane]);
        asm volatile("cp.async.cg.shared.global [%0], [%1], 16;\n"
                     :: "r"(dst), "l"(&Ar[i * 32 + lane]) : "memory");
    }
    asm volatile("cp.async.commit_group;\n" ::: "memory");

#pragma unroll 1
    for (int t = 0; t < NT; t++) {
        const int buf = t & 1;
        if (t + 1 < NT) {
            const int nbuf = buf ^ 1;
#pragma unroll
            for (int i = 0; i < CPT; i++) {
                unsigned dst = (unsigned)__cvta_generic_to_shared(&s_a[wid][nbuf][i][lane]);
                asm volatile("cp.async.cg.shared.global [%0], [%1], 16;\n"
                             :: "r"(dst), "l"(&Ar[((t + 1) * CPT + i) * 32 + lane]) : "memory");
            }
            asm volatile("cp.async.commit_group;\n" ::: "memory");
            asm volatile("cp.async.wait_group 1;\n" ::: "memory");
        } else {
            asm volatile("cp.async.wait_group 0;\n" ::: "memory");
        }
        int cnt = 0;
#pragma unroll
        for (int i = 0; i < CPT; i++) {
            float4 a = s_a[wid][buf][i][lane];
            int gchunk = t * CPT + i;
#pragma unroll
            for (int c = 0; c < 4; c++) {
                float comp = (c == 0) ? a.x : (c == 1) ? a.y : (c == 2) ? a.z : a.w;
                unsigned m = __ballot_sync(0xffffffffu, comp != 0.f);
                if (!m) continue;
                int k = __popc(m);
                if (cnt + k <= SP_CAP) {
                    if (comp != 0.f) {
                        int pos = cnt + __popc(m & ((1u << lane) - 1u));
                        s_val[wid][pos] = comp;
                        s_col[wid][pos] = gchunk * 128 + lane * 4 + c;
                    }
                    cnt += k;
                } else {          // overflow fallback (effectively never taken)
                    while (m) {
                        int b = __ffs(m) - 1; m &= m - 1;
                        float av = __shfl_sync(0xffffffffu, comp, b);
                        float4 x = X4[(size_t)(gchunk * 128 + b * 4 + c) * 32 + lane];
                        acc.x += av * x.x; acc.y += av * x.y;
                        acc.z += av * x.z; acc.w += av * x.w;
                    }
                }
            }
        }
        __syncwarp();
        for (int g = 0; g < cnt; g += 4) {
            float av0 = 0.f, av1 = 0.f, av2 = 0.f, av3 = 0.f;
            int n = cnt - g;
            av0 = s_val[wid][g];
            int c0i = s_col[wid][g];
            int c1i = (n > 1) ? s_col[wid][g + 1] : c0i;
            int c2i = (n > 2) ? s_col[wid][g + 2] : c0i;
            int c3i = (n > 3) ? s_col[wid][g + 3] : c0i;
            if (n > 1) av1 = s_val[wid][g + 1];
            if (n > 2) av2 = s_val[wid][g + 2];
            if (n > 3) av3 = s_val[wid][g + 3];
            float4 x0 = X4[(size_t)c0i * 32 + lane];
            float4 x1 = X4[(size_t)c1i * 32 + lane];
            float4 x2 = X4[(size_t)c2i * 32 + lane];
            float4 x3 = X4[(size_t)c3i * 32 + lane];
            acc.x += av0 * x0.x + av1 * x1.x + av2 * x2.x + av3 * x3.x;
            acc.y += av0 * x0.y + av1 * x1.y + av2 * x2.y + av3 * x3.y;
            acc.z += av0 * x0.z + av1 * x1.z + av2 * x2.z + av3 * x3.z;
            acc.w += av0 * x0.w + av1 * x1.w + av2 * x2.w + av3 * x3.w;
        }
        __syncwarp();
    }
    ((float4*)g_dif)[(size_t)row * 32 + lane] = acc;
}

// ---------------- reduce moment partials ----------------
__global__ void k_Hred() {
    int p = blockIdx.x;          // NC blocks
    int tid = threadIdx.x;       // 512 threads
    int q4 = tid >> 7, d = tid & 127;
    __shared__ float red[4][128];
    float sum = 0.f;
#pragma unroll
    for (int q = 0; q < 32; q++)
        sum += g_part[((size_t)(q4 * 32 + q) * NC + p) * 128 + d];
    red[q4][d] = sum;
    __syncthreads();
    if (q4 == 0) g_G[p * 128 + d] = red[0][d] + red[1][d] + red[2][d] + red[3][d];
}

// ---------------- final: H/h combine + per-row poly eval + blend -------------
__global__ void k_final(float* __restrict__ out) {
    int d = threadIdx.x;   // 128
    float Gp[NC];
#pragma unroll
    for (int p = 0; p < NC; p++) Gp[p] = g_G[p * 128 + d];
    float Hl[NC];
#pragma unroll
    for (int l = 0; l < NC; l++) {
        float s = 0.f;
#pragma unroll
        for (int p = 0; p < NC; p++) if (p <= DEG - l) s += g_B[l * 32 + p] * Gp[p];
        Hl[l] = s;
    }
    __shared__ float hs[NC];
    if (d < NC) {
        float s = 0.f;
        for (int p = 0; p <= DEG - d; p++) s += g_B[d * 32 + p] * g_G2[p];
        hs[d] = s;
    }
    __syncthreads();
    float omega = g_scal[0], delta = g_scal[1], center = g_scal[2], inv2h = g_scal[3];
    int i0 = blockIdx.x * 32;
    for (int r = 0; r < 32; r++) {
        int i = i0 + r;
        float sig = (g_s[i] - center) * inv2h;
        float pw = 1.f, num = 0.f, den = 0.f;
#pragma unroll
        for (int l = 0; l < NC; l++) { num += pw * Hl[l]; den += pw * hs[l]; pw *= sig; }
        float con = num / den;
        float dif = g_dif[(size_t)i * 128 + d];
        float rea = g_rea[(size_t)i * 128 + d];
        out[(size_t)i * 128 + d] = omega * fmaxf(dif, 0.f) + (1.f - omega) * con + delta * rea;
    }
}

// ---------------- launch (R10 schedule, k_A hoisted before k_s) --------------
static cudaStream_t g_s1, g_s2;
static cudaEvent_t g_evS, g_evA, g_evSp, g_evRea, g_evSetup;
static bool g_init = false;

extern "C" void kernel_launch(void* const* d_in, const int* in_sizes, int n_in,
                              void* d_out, int out_size) {
    const float* Z   = (const float*)d_in[0];
    const float* A   = (const float*)d_in[1];
    const float* W_D = (const float*)d_in[2];
    const float* W_C = (const float*)d_in[3];
    const float* w_V = (const float*)d_in[4];
    const float* W1  = (const float*)d_in[5];
    const float* b1  = (const float*)d_in[6];
    const float* W2  = (const float*)d_in[7];
    const float* b2  = (const float*)d_in[8];
    const float* omL = (const float*)d_in[9];
    const float* dlL = (const float*)d_in[10];
    float* out = (float*)d_out;

    if (!g_init) {   // one-time host resource creation (no device memory)
        cudaStreamCreateWithFlags(&g_s1, cudaStreamNonBlocking);
        cudaStreamCreateWithFlags(&g_s2, cudaStreamNonBlocking);
        cudaEventCreateWithFlags(&g_evS, cudaEventDisableTiming);
        cudaEventCreateWithFlags(&g_evA, cudaEventDisableTiming);
        cudaEventCreateWithFlags(&g_evSp, cudaEventDisableTiming);
        cudaEventCreateWithFlags(&g_evRea, cudaEventDisableTiming);
        cudaEventCreateWithFlags(&g_evSetup, cudaEventDisableTiming);
        g_init = true;
    }

    // 1: three big GEMMs first (spmm's only prerequisite)
    k_A<<<384, 256>>>(Z, W_D, W_C, W1, b1);
    cudaEventRecord(g_evA, 0);

    // 2: s vector (after evA so spmm's prefix excludes it)
    k_s<<<1024, 256>>>(Z, w_V);
    cudaEventRecord(g_evS, 0);

    // 3: setup on s2 (needs only g_s)
    cudaStreamWaitEvent(g_s2, g_evS, 0);
    k_setup<<<1, 1024, 0, g_s2>>>(omL, dlL);
    cudaEventRecord(g_evSetup, g_s2);

    // 4: spmm on s1 after k_A only   <- ncu captures this
    cudaStreamWaitEvent(g_s1, g_evA, 0);
    k_spmm<<<2048, 128, 0, g_s1>>>(A);
    cudaEventRecord(g_evSp, g_s1);

    // 5: rea GEMM on s2 after k_A
    cudaStreamWaitEvent(g_s2, g_evA, 0);
    k_rea<<<128, 256, 0, g_s2>>>(W2, b2);
    cudaEventRecord(g_evRea, g_s2);

    // 6-7: moment chain on main (needs k_A output + setup scalars)
    cudaStreamWaitEvent(0, g_evSetup, 0);
    k_mom<<<65, 256>>>();
    k_Hred<<<NC, 512>>>();

    // 8: join
    cudaStreamWaitEvent(0, g_evSp, 0);
    cudaStreamWaitEvent(0, g_evRea, 0);
    k_final<<<256, 128>>>(out);
}

// round 14
// speedup vs baseline: 1.1750x; 1.1750x over previous
#include <cuda_runtime.h>
#include <math.h>

#define NN 8192
#define DD 128
#define DEG 26
#define NC (DEG + 1)
#define NPART 128

// ---------------- scratch (device globals; no allocations) ----------------
__device__ float g_Xd[NN * DD];      // Z @ W_D^T
__device__ float g_Hh[NN * DD];      // tanh(Z @ W1^T + b1)
__device__ float g_rea[NN * DD];     // H @ W2^T + b2
__device__ float g_dif[NN * DD];     // A_norm @ Xd (pre-relu)
__device__ float g_s[NN];            // Z @ w_V
__device__ float g_B[32 * 32];       // separable poly combination matrix
__device__ float g_scal[8];          // omega, delta, center, inv2h
__device__ float g_part[NPART * NC * DD];
__device__ float g_T[NC * DD];       // T = P @ Z  (moments of Z)
__device__ float g_G[NC * DD];       // G = T @ W_C^T (moments of Xc)
__device__ float g_G2[NC];           // scalar moments

// ---------------- 64x128 register-tiled SGEMM ----------------
__device__ __forceinline__ void gemm_tile(const float* __restrict__ In,
                                          const float* __restrict__ W,
                                          const float* __restrict__ bias,
                                          float* __restrict__ Out,
                                          int row0, bool doTanh) {
    __shared__ float Zs[32][68];
    __shared__ float Ws[32][132];
    const int tid = threadIdx.x;           // 256 threads
    const int tx = tid & 31, ty = tid >> 5;
    const int c0 = tx * 4, r0 = ty * 8;
    float4 acc[8];
#pragma unroll
    for (int i = 0; i < 8; i++) acc[i] = make_float4(0.f, 0.f, 0.f, 0.f);

    for (int kc = 0; kc < 128; kc += 32) {
#pragma unroll
        for (int i = 0; i < 8; i++) {
            int idx = tid + i * 256;
            int r = idx >> 5, k = idx & 31;
            Zs[k][r] = In[(size_t)(row0 + r) * 128 + kc + k];
        }
#pragma unroll
        for (int i = 0; i < 16; i++) {
            int idx = tid + i * 256;
            int c = idx >> 5, k = idx & 31;
            Ws[k][c] = W[(size_t)c * 128 + kc + k];
        }
        __syncthreads();
#pragma unroll
        for (int k = 0; k < 32; k++) {
            float4 w  = *(const float4*)&Ws[k][c0];
            float4 z0 = *(const float4*)&Zs[k][r0];
            float4 z1 = *(const float4*)&Zs[k][r0 + 4];
            acc[0].x += z0.x * w.x; acc[0].y += z0.x * w.y; acc[0].z += z0.x * w.z; acc[0].w += z0.x * w.w;
            acc[1].x += z0.y * w.x; acc[1].y += z0.y * w.y; acc[1].z += z0.y * w.z; acc[1].w += z0.y * w.w;
            acc[2].x += z0.z * w.x; acc[2].y += z0.z * w.y; acc[2].z += z0.z * w.z; acc[2].w += z0.z * w.w;
            acc[3].x += z0.w * w.x; acc[3].y += z0.w * w.y; acc[3].z += z0.w * w.z; acc[3].w += z0.w * w.w;
            acc[4].x += z1.x * w.x; acc[4].y += z1.x * w.y; acc[4].z += z1.x * w.z; acc[4].w += z1.x * w.w;
            acc[5].x += z1.y * w.x; acc[5].y += z1.y * w.y; acc[5].z += z1.y * w.z; acc[5].w += z1.y * w.w;
            acc[6].x += z1.z * w.x; acc[6].y += z1.z * w.y; acc[6].z += z1.z * w.z; acc[6].w += z1.z * w.w;
            acc[7].x += z1.w * w.x; acc[7].y += z1.w * w.y; acc[7].z += z1.w * w.z; acc[7].w += z1.w * w.w;
        }
        __syncthreads();
    }
    float4 bv = make_float4(0.f, 0.f, 0.f, 0.f);
    if (bias) bv = *(const float4*)&bias[c0];
#pragma unroll
    for (int i = 0; i < 8; i++) {
        float4 v = acc[i];
        v.x += bv.x; v.y += bv.y; v.z += bv.z; v.w += bv.w;
        if (doTanh) { v.x = tanhf(v.x); v.y = tanhf(v.y); v.z = tanhf(v.z); v.w = tanhf(v.w); }
        *(float4*)&Out[(size_t)(row0 + r0 + i) * 128 + c0] = v;
    }
}

// ---------------- s = Z @ w_V ----------------
__global__ void k_s(const float* __restrict__ Z, const float* __restrict__ wv) {
    int warp = (blockIdx.x * blockDim.x + threadIdx.x) >> 5;   // 8192 warps
    int lane = threadIdx.x & 31;
    const float* z = Z + (size_t)warp * 128;
    float acc = z[lane] * wv[lane] + z[lane + 32] * wv[lane + 32] +
                z[lane + 64] * wv[lane + 64] + z[lane + 96] * wv[lane + 96];
#pragma unroll
    for (int o = 16; o > 0; o >>= 1) acc += __shfl_xor_sync(0xffffffffu, acc, o);
    if (lane == 0) g_s[warp] = acc;
}

// ---------------- A: two GEMMs (Xd, Hh) — Xc eliminated algebraically -------
__global__ void k_A(const float* __restrict__ Z, const float* __restrict__ WD,
                    const float* __restrict__ W1, const float* __restrict__ b1) {
    int which = blockIdx.x >> 7;
    int row0 = (blockIdx.x & 127) * 64;
    if (which == 0) gemm_tile(Z, WD, nullptr, g_Xd, row0, false);
    else            gemm_tile(Z, W1, b1,      g_Hh, row0, true);
}

// ---------------- rea = Hh @ W2^T + b2 ----------------
__global__ void k_rea(const float* __restrict__ W2, const float* __restrict__ b2) {
    gemm_tile(g_Hh, W2, b2, g_rea, blockIdx.x * 64, false);
}

// ---------------- setup: minmax + Chebyshev fit + B matrix ----------------
__global__ void k_setup(const float* __restrict__ om_l, const float* __restrict__ dl_l) {
    const int t = threadIdx.x;             // 1024 threads
    const int wid = t >> 5, lane = t & 31;
    __shared__ float slo[1024], shi[1024];
    __shared__ double sh_fm[64], sh_th[64];
    __shared__ double sh_cs[NC];
    __shared__ double sh_bm[32];
    __shared__ double sh_pas[32][33];
    __shared__ double sh_hc[2];

    float lo = 1e30f, hi = -1e30f;
#pragma unroll
    for (int r = 0; r < 8; r++) { float v = g_s[t + r * 1024]; lo = fminf(lo, v); hi = fmaxf(hi, v); }
    slo[t] = lo; shi[t] = hi; __syncthreads();
    for (int st = 512; st > 0; st >>= 1) {
        if (t < st) { slo[t] = fminf(slo[t], slo[t + st]); shi[t] = fmaxf(shi[t], shi[t + st]); }
        __syncthreads();
    }
    if (t == 0) {
        double dlo = (double)slo[0], dhi = (double)shi[0];
        sh_hc[0] = 0.5 * (dlo + dhi);
        sh_hc[1] = 0.5 * (dhi - dlo) + 1e-12;
    }
    __syncthreads();
    const double half = sh_hc[1];
    const double PI = 3.14159265358979323846;

    if (t < 64) {
        double th = PI * (t + 0.5) / 64.0;
        double vm = cos(th);
        sh_th[t] = th;
        sh_fm[t] = exp(1.0 / (1.0 + exp(-2.0 * half * vm)));
    }
    __syncthreads();

    if (wid < NC) {
        double acc = sh_fm[lane] * cos((double)wid * sh_th[lane])
                   + sh_fm[lane + 32] * cos((double)wid * sh_th[lane + 32]);
#pragma unroll
        for (int o = 16; o > 0; o >>= 1)
            acc += __shfl_xor_sync(0xffffffffu, acc, o);
        if (lane == 0) sh_cs[wid] = acc * (2.0 / 64.0) * (wid == 0 ? 0.5 : 1.0);
    }
    if (wid == 31) {                           // Pascal's triangle
        double cur = (lane == 0) ? 1.0 : 0.0;
        sh_pas[0][lane] = cur;
        for (int n = 1; n < 32; n++) {
            double up = __shfl_up_sync(0xffffffffu, cur, 1);
            if (lane == 0) up = 0.0;
            cur += up;
            sh_pas[n][lane] = cur;
        }
    }
    __syncthreads();

    if (wid == 0) {                            // Chebyshev -> monomial
        double mprev = (lane == 0) ? 1.0 : 0.0;
        double mcur  = (lane == 1) ? 1.0 : 0.0;
        double bm = sh_cs[0] * mprev + sh_cs[1] * mcur;
        for (int k = 2; k < NC; k++) {
            double sh = __shfl_up_sync(0xffffffffu, mcur, 1);
            if (lane == 0) sh = 0.0;
            double mnext = 2.0 * sh - mprev;
            bm += sh_cs[k] * mnext;
            mprev = mcur; mcur = mnext;
        }
        sh_bm[lane] = bm;
    }
    __syncthreads();

    {
        int l = t >> 5, p = t & 31;
        float val = 0.f;
        if (l <= DEG && p <= DEG - l) {
            double v = sh_bm[l + p] * sh_pas[l + p][l];
            if (p & 1) v = -v;
            val = (float)v;
        }
        g_B[t] = val;
    }
    if (t == 0) {
        g_scal[0] = 1.f / (1.f + expf(-om_l[0]));  // omega
        g_scal[1] = 1.f / (1.f + expf(-dl_l[0]));  // delta
        g_scal[2] = (float)sh_hc[0];               // center
        g_scal[3] = (float)(0.5 / half);           // 1/(2*half)
    }
}

// ---------------- moments of Z: T partials + scalar moments (needs only s,Z) -
__global__ void k_mom(const float* __restrict__ Z) {
    int bx = blockIdx.x;      // 65 blocks
    int tid = threadIdx.x;    // 256
    float center = g_scal[2], inv2h = g_scal[3];
    if (bx < 64) {
        int h = tid >> 7, d = tid & 127;
        int part = bx * 2 + h;
        int j0 = bx * 128 + h * 64;
        float acc[NC];
#pragma unroll
        for (int p = 0; p < NC; p++) acc[p] = 0.f;
#pragma unroll 2
        for (int jj = 0; jj < 64; jj++) {
            int j = j0 + jj;
            float sig = (g_s[j] - center) * inv2h;
            float x = Z[(size_t)j * 128 + d];
            float sig2 = sig * sig;
            float pe = x, po = x * sig;
            acc[0] += pe; acc[1] += po;
#pragma unroll
            for (int p = 2; p < NC; p += 2) {
                pe *= sig2; acc[p] += pe;
                if (p + 1 < NC) { po *= sig2; acc[p + 1] += po; }
            }
        }
#pragma unroll
        for (int p = 0; p < NC; p++) g_part[((size_t)part * NC + p) * 128 + d] = acc[p];
    } else {
        float acc[NC];
#pragma unroll
        for (int p = 0; p < NC; p++) acc[p] = 0.f;
#pragma unroll 2
        for (int jj = 0; jj < 32; jj++) {
            int j = tid + jj * 256;
            float sig = (g_s[j] - center) * inv2h;
            float sig2 = sig * sig;
            float pe = 1.f, po = sig;
            acc[0] += pe; acc[1] += po;
#pragma unroll
            for (int p = 2; p < NC; p += 2) {
                pe *= sig2; acc[p] += pe;
                if (p + 1 < NC) { po *= sig2; acc[p + 1] += po; }
            }
        }
        __shared__ float red2[8][NC];
        int wid = tid >> 5, lane = tid & 31;
#pragma unroll
        for (int p = 0; p < NC; p++) {
            float v = acc[p];
#pragma unroll
            for (int o = 16; o > 0; o >>= 1) v += __shfl_xor_sync(0xffffffffu, v, o);
            if (lane == 0) red2[wid][p] = v;
        }
        __syncthreads();
        if (tid < NC) {
            float s = 0.f;
#pragma unroll
            for (int w = 0; w < 8; w++) s += red2[w][tid];
            g_G2[tid] = s;
        }
    }
}

// ---------------- reduce moment partials -> T ----------------
__global__ void k_Hred() {
    int p = blockIdx.x;          // NC blocks
    int tid = threadIdx.x;       // 512 threads
    int q4 = tid >> 7, d = tid & 127;
    __shared__ float red[4][128];
    float sum = 0.f;
#pragma unroll
    for (int q = 0; q < 32; q++)
        sum += g_part[((size_t)(q4 * 32 + q) * NC + p) * 128 + d];
    red[q4][d] = sum;
    __syncthreads();
    if (q4 == 0) g_T[p * 128 + d] = red[0][d] + red[1][d] + red[2][d] + red[3][d];
}

// ---------------- G = T @ W_C^T  (tiny: 27x128 @ 128x128) --------------------
__global__ void k_Gc(const float* __restrict__ WC) {
    __shared__ float Ts[NC][DD];
    int d = threadIdx.x;   // 128
    for (int p = 0; p < NC; p++) Ts[p][d] = g_T[p * 128 + d];
    __syncthreads();
    // thread d owns WC row d (L1-resident after first pass)
    const float4* wc = (const float4*)(WC + (size_t)d * 128);
    for (int p = 0; p < NC; p++) {
        float s = 0.f;
#pragma unroll
        for (int e = 0; e < 32; e++) {
            float4 w = wc[e];
            s += Ts[p][e * 4] * w.x + Ts[p][e * 4 + 1] * w.y +
                 Ts[p][e * 4 + 2] * w.z + Ts[p][e * 4 + 3] * w.w;
        }
        g_G[p * 128 + d] = s;
    }
}

// ---------------- spmm: cp.async-staged A stream, warp per row ---------------
#define SP_CAP 64
#define CPT 4     // chunks per tile (chunk = 32 float4 = 512B per warp)
#define NT 16     // tiles per row (64 chunks total)

__global__ void __launch_bounds__(128, 12)
k_spmm(const float* __restrict__ A) {
    __shared__ __align__(16) float4 s_a[4][2][CPT][32];   // 16KB
    __shared__ float s_val[4][SP_CAP];
    __shared__ int   s_col[4][SP_CAP];
    const int wid = threadIdx.x >> 5;
    const int lane = threadIdx.x & 31;
    const int row = blockIdx.x * 4 + wid;
    const float4* __restrict__ Ar = (const float4*)(A + (size_t)row * NN);
    const float4* __restrict__ X4 = (const float4*)g_Xd;
    float4 acc = make_float4(0.f, 0.f, 0.f, 0.f);

#pragma unroll
    for (int i = 0; i < CPT; i++) {
        unsigned dst = (unsigned)__cvta_generic_to_shared(&s_a[wid][0][i][lane]);
        asm volatile("cp.async.cg.shared.global [%0], [%1], 16;\n"
                     :: "r"(dst), "l"(&Ar[i * 32 + lane]) : "memory");
    }
    asm volatile("cp.async.commit_group;\n" ::: "memory");

#pragma unroll 1
    for (int t = 0; t < NT; t++) {
        const int buf = t & 1;
        if (t + 1 < NT) {
            const int nbuf = buf ^ 1;
#pragma unroll
            for (int i = 0; i < CPT; i++) {
                unsigned dst = (unsigned)__cvta_generic_to_shared(&s_a[wid][nbuf][i][lane]);
                asm volatile("cp.async.cg.shared.global [%0], [%1], 16;\n"
                             :: "r"(dst), "l"(&Ar[((t + 1) * CPT + i) * 32 + lane]) : "memory");
            }
            asm volatile("cp.async.commit_group;\n" ::: "memory");
            asm volatile("cp.async.wait_group 1;\n" ::: "memory");
        } else {
            asm volatile("cp.async.wait_group 0;\n" ::: "memory");
        }
        int cnt = 0;
#pragma unroll
        for (int i = 0; i < CPT; i++) {
            float4 a = s_a[wid][buf][i][lane];
            int gchunk = t * CPT + i;
#pragma unroll
            for (int c = 0; c < 4; c++) {
                float comp = (c == 0) ? a.x : (c == 1) ? a.y : (c == 2) ? a.z : a.w;
                unsigned m = __ballot_sync(0xffffffffu, comp != 0.f);
                if (!m) continue;
                int k = __popc(m);
                if (cnt + k <= SP_CAP) {
                    if (comp != 0.f) {
                        int pos = cnt + __popc(m & ((1u << lane) - 1u));
                        s_val[wid][pos] = comp;
                        s_col[wid][pos] = gchunk * 128 + lane * 4 + c;
                    }
                    cnt += k;
                } else {
                    while (m) {
                        int b = __ffs(m) - 1; m &= m - 1;
                        float av = __shfl_sync(0xffffffffu, comp, b);
                        float4 x = X4[(size_t)(gchunk * 128 + b * 4 + c) * 32 + lane];
                        acc.x += av * x.x; acc.y += av * x.y;
                        acc.z += av * x.z; acc.w += av * x.w;
                    }
                }
            }
        }
        __syncwarp();
        for (int g = 0; g < cnt; g += 4) {
            float av0 = 0.f, av1 = 0.f, av2 = 0.f, av3 = 0.f;
            int n = cnt - g;
            av0 = s_val[wid][g];
            int c0i = s_col[wid][g];
            int c1i = (n > 1) ? s_col[wid][g + 1] : c0i;
            int c2i = (n > 2) ? s_col[wid][g + 2] : c0i;
            int c3i = (n > 3) ? s_col[wid][g + 3] : c0i;
            if (n > 1) av1 = s_val[wid][g + 1];
            if (n > 2) av2 = s_val[wid][g + 2];
            if (n > 3) av3 = s_val[wid][g + 3];
            float4 x0 = X4[(size_t)c0i * 32 + lane];
            float4 x1 = X4[(size_t)c1i * 32 + lane];
            float4 x2 = X4[(size_t)c2i * 32 + lane];
            float4 x3 = X4[(size_t)c3i * 32 + lane];
            acc.x += av0 * x0.x + av1 * x1.x + av2 * x2.x + av3 * x3.x;
            acc.y += av0 * x0.y + av1 * x1.y + av2 * x2.y + av3 * x3.y;
            acc.z += av0 * x0.z + av1 * x1.z + av2 * x2.z + av3 * x3.z;
            acc.w += av0 * x0.w + av1 * x1.w + av2 * x2.w + av3 * x3.w;
        }
        __syncwarp();
    }
    ((float4*)g_dif)[(size_t)row * 32 + lane] = acc;
}

// ---------------- final: H/h combine + per-row poly eval + blend -------------
__global__ void k_final(float* __restrict__ out) {
    int d = threadIdx.x;   // 128
    float Gp[NC];
#pragma unroll
    for (int p = 0; p < NC; p++) Gp[p] = g_G[p * 128 + d];
    float Hl[NC];
#pragma unroll
    for (int l = 0; l < NC; l++) {
        float s = 0.f;
#pragma unroll
        for (int p = 0; p < NC; p++) if (p <= DEG - l) s += g_B[l * 32 + p] * Gp[p];
        Hl[l] = s;
    }
    __shared__ float hs[NC];
    if (d < NC) {
        float s = 0.f;
        for (int p = 0; p <= DEG - d; p++) s += g_B[d * 32 + p] * g_G2[p];
        hs[d] = s;
    }
    __syncthreads();
    float omega = g_scal[0], delta = g_scal[1], center = g_scal[2], inv2h = g_scal[3];
    int i0 = blockIdx.x * 32;
    for (int r = 0; r < 32; r++) {
        int i = i0 + r;
        float sig = (g_s[i] - center) * inv2h;
        float pw = 1.f, num = 0.f, den = 0.f;
#pragma unroll
        for (int l = 0; l < NC; l++) { num += pw * Hl[l]; den += pw * hs[l]; pw *= sig; }
        float con = num / den;
        float dif = g_dif[(size_t)i * 128 + d];
        float rea = g_rea[(size_t)i * 128 + d];
        out[(size_t)i * 128 + d] = omega * fmaxf(dif, 0.f) + (1.f - omega) * con + delta * rea;
    }
}

// ---------------- launch ----------------
static cudaStream_t g_s1, g_s2;
static cudaEvent_t g_evS, g_evA, g_evSp, g_evG;
static bool g_init = false;

extern "C" void kernel_launch(void* const* d_in, const int* in_sizes, int n_in,
                              void* d_out, int out_size) {
    const float* Z   = (const float*)d_in[0];
    const float* A   = (const float*)d_in[1];
    const float* W_D = (const float*)d_in[2];
    const float* W_C = (const float*)d_in[3];
    const float* w_V = (const float*)d_in[4];
    const float* W1  = (const float*)d_in[5];
    const float* b1  = (const float*)d_in[6];
    const float* W2  = (const float*)d_in[7];
    const float* b2  = (const float*)d_in[8];
    const float* omL = (const float*)d_in[9];
    const float* dlL = (const float*)d_in[10];
    float* out = (float*)d_out;

    if (!g_init) {   // one-time host resource creation (no device memory)
        cudaStreamCreateWithFlags(&g_s1, cudaStreamNonBlocking);
        cudaStreamCreateWithFlags(&g_s2, cudaStreamNonBlocking);
        cudaEventCreateWithFlags(&g_evS, cudaEventDisableTiming);
        cudaEventCreateWithFlags(&g_evA, cudaEventDisableTiming);
        cudaEventCreateWithFlags(&g_evSp, cudaEventDisableTiming);
        cudaEventCreateWithFlags(&g_evG, cudaEventDisableTiming);
        g_init = true;
    }

    // 1: s vector (unblocks the whole moment chain)
    k_s<<<1024, 256>>>(Z, w_V);
    cudaEventRecord(g_evS, 0);

    // 2: two big GEMMs (Xd + Hh) on main
    k_A<<<256, 256>>>(Z, W_D, W1, b1);
    cudaEventRecord(g_evA, 0);

    // 3: setup on s2 (needs only g_s)
    cudaStreamWaitEvent(g_s2, g_evS, 0);
    k_setup<<<1, 1024, 0, g_s2>>>(omL, dlL);

    // 4: spmm on s1 after k_A   <- ncu captures this
    cudaStreamWaitEvent(g_s1, g_evA, 0);
    k_spmm<<<2048, 128, 0, g_s1>>>(A);
    cudaEventRecord(g_evSp, g_s1);

    // 5-7: moment chain on s2 — reads Z, independent of k_A, hides inside it
    k_mom<<<65, 256, 0, g_s2>>>(Z);
    k_Hred<<<NC, 512, 0, g_s2>>>();
    k_Gc<<<1, 128, 0, g_s2>>>(W_C);
    cudaEventRecord(g_evG, g_s2);

    // 8: rea GEMM on main after k_A (only contender during spmm window)
    k_rea<<<128, 256>>>(W2, b2);

    // 9: join
    cudaStreamWaitEvent(0, g_evSp, 0);
    cudaStreamWaitEvent(0, g_evG, 0);
    k_final<<<256, 128>>>(out);
}